// round 1
// baseline (speedup 1.0000x reference)
#include <cuda_runtime.h>
#include <cuda_bf16.h>
#include <math.h>

// ---------------- static problem sizes (from reference setup_inputs) -------
#define NMAX 100352      // >= N=100000
#define EMAX 1000448     // >= E=1000000
#define DF   64          // input feature dim
#define HH   128         // hidden
#define HHF  64          // H/2
#define CCH  40          // classes

// ---------------- device scratch (no allocations allowed) ------------------
__device__ float g_F1 [NMAX * DF];   // phase-1 result -> phase-2 feat_0
__device__ float g_F2 [NMAX * DF];   // phase-2 result (h) -> MLP input
__device__ float g_FSa[NMAX * DF];   // scaled feature ping
__device__ float g_FSb[NMAX * DF];   // scaled feature pong
__device__ float g_t1 [NMAX * HH];   // MLP intermediate
__device__ float g_t2 [NMAX * HHF];  // MLP intermediate
__device__ int   g_din [NMAX];
__device__ int   g_dout[NMAX];
__device__ int   g_cur [NMAX];
__device__ int   g_rowptr[NMAX + 1];
__device__ int   g_csrc[EMAX];
__device__ float g_snorm[NMAX];
__device__ float g_dnorm[NMAX];

// ---------------- preprocessing kernels ------------------------------------
__global__ void zero_kernel(int n) {
    int i = blockIdx.x * blockDim.x + threadIdx.x;
    if (i < n) { g_din[i] = 0; g_dout[i] = 0; g_cur[i] = 0; }
}

__global__ void deg_kernel(const int* __restrict__ src, const int* __restrict__ dst, int e) {
    int i = blockIdx.x * blockDim.x + threadIdx.x;
    if (i < e) {
        atomicAdd(&g_dout[src[i]], 1);
        atomicAdd(&g_din [dst[i]], 1);
    }
}

__global__ void norm_kernel(int n) {
    int i = blockIdx.x * blockDim.x + threadIdx.x;
    if (i < n) {
        int o = g_dout[i];
        int d = g_din[i];
        g_snorm[i] = (o > 0) ? rsqrtf((float)o) : 0.0f;
        g_dnorm[i] = (d > 0) ? rsqrtf((float)d) : 0.0f;
    }
}

// single-block exclusive scan of g_din -> g_rowptr (n up to ~100K)
__global__ void scan_kernel(int n) {
    __shared__ int sums[1024];
    int t = threadIdx.x;
    int per = (n + 1023) / 1024;
    int beg = t * per;
    int end = min(beg + per, n);
    int s = 0;
    for (int i = beg; i < end; i++) s += g_din[i];
    sums[t] = s;
    __syncthreads();
    for (int off = 1; off < 1024; off <<= 1) {
        int v = 0;
        if (t >= off) v = sums[t - off];
        __syncthreads();
        sums[t] += v;
        __syncthreads();
    }
    int run = (t == 0) ? 0 : sums[t - 1];
    for (int i = beg; i < end; i++) { g_rowptr[i] = run; run += g_din[i]; }
    if (end == n) g_rowptr[n] = run;   // all tail threads write the same total
}

__global__ void scatter_kernel(const int* __restrict__ src, const int* __restrict__ dst, int e) {
    int i = blockIdx.x * blockDim.x + threadIdx.x;
    if (i < e) {
        int d = dst[i];
        int p = g_rowptr[d] + atomicAdd(&g_cur[d], 1);
        g_csrc[p] = src[i];
    }
}

__global__ void initfs_kernel(const float* __restrict__ feat, int n) {
    int i = blockIdx.x * blockDim.x + threadIdx.x;
    if (i < n * DF) {
        int node = i >> 6;
        g_FSa[i] = feat[i] * g_snorm[node];
    }
}

// ---------------- APPNP propagation step (warp-per-node, pull/CSR) ---------
// ab:   0 -> read FSa, write FSb ; 1 -> read FSb, write FSa
// f0_ext: feat_0 pointer for phase 1 (input features); nullptr -> use g_F1
// fo:   0 none, 1 -> also write unscaled f into g_F1, 2 -> into g_F2
__global__ __launch_bounds__(256) void appnp_step(const float* __restrict__ f0_ext,
                                                  int ab, int fo, int n) {
    int warp = blockIdx.x * (blockDim.x >> 5) + (threadIdx.x >> 5);
    int lane = threadIdx.x & 31;
    if (warp >= n) return;

    const float* __restrict__ fs_in  = ab ? g_FSb : g_FSa;
    float*       __restrict__ fs_out = ab ? g_FSa : g_FSb;
    const float* __restrict__ f0     = f0_ext ? f0_ext : g_F1;

    int beg = g_rowptr[warp];
    int end = g_rowptr[warp + 1];

    float ax = 0.0f, ay = 0.0f;
    int off2 = 2 * lane;                       // this lane owns cols 2*lane, 2*lane+1
    for (int e = beg; e < end; e++) {
        int s = __ldg(&g_csrc[e]);             // warp-uniform
        float2 v = *(const float2*)(fs_in + (size_t)s * DF + off2);
        ax += v.x; ay += v.y;
    }

    float dn = g_dnorm[warp];
    float sn = g_snorm[warp];
    size_t o = (size_t)warp * DF + off2;
    float2 f0v = *(const float2*)(f0 + o);
    float fx = 0.9f * ax * dn + 0.1f * f0v.x;
    float fy = 0.9f * ay * dn + 0.1f * f0v.y;

    *(float2*)(fs_out + o) = make_float2(fx * sn, fy * sn);
    if (fo == 1) *(float2*)(g_F1 + o) = make_float2(fx, fy);
    else if (fo == 2) *(float2*)(g_F2 + o) = make_float2(fx, fy);
}

// ---------------- simple smem-tiled SGEMM: C = [relu](A[MxK] @ W[KxNC] + b) -
// 256 threads, 64 rows per block. Each thread: row = tid/4, computes NC/4 cols
// with column stride 4 (conflict-free smem reads).
template<int K, int NC, bool RELU>
__global__ __launch_bounds__(256) void gemm_kernel(const float* __restrict__ A,
                                                   const float* __restrict__ W,
                                                   const float* __restrict__ bias,
                                                   float* __restrict__ C, int M) {
    __shared__ float sA[64][33];
    __shared__ float sW[32][NC];
    const int CPT = NC / 4;
    float acc[CPT];
    int tid = threadIdx.x;
    int r  = tid >> 2;
    int cg = tid & 3;
    int row = blockIdx.x * 64 + r;
#pragma unroll
    for (int c = 0; c < CPT; c++) acc[c] = 0.0f;

    for (int kk = 0; kk < K; kk += 32) {
        for (int i = tid; i < 64 * 32; i += 256) {
            int rr = i >> 5, kx = i & 31;
            int grow = blockIdx.x * 64 + rr;
            sA[rr][kx] = (grow < M) ? A[(size_t)grow * K + kk + kx] : 0.0f;
        }
        for (int i = tid; i < 32 * NC; i += 256) {
            int kx = i / NC, cx = i % NC;
            sW[kx][cx] = W[(size_t)(kk + kx) * NC + cx];
        }
        __syncthreads();
#pragma unroll
        for (int k = 0; k < 32; k++) {
            float a = sA[r][k];
#pragma unroll
            for (int c = 0; c < CPT; c++) acc[c] += a * sW[k][c * 4 + cg];
        }
        __syncthreads();
    }

    if (row < M) {
#pragma unroll
        for (int c = 0; c < CPT; c++) {
            float v = acc[c] + bias[c * 4 + cg];
            if (RELU) v = fmaxf(v, 0.0f);
            C[(size_t)row * NC + c * 4 + cg] = v;
        }
    }
}

// ---------------- launch ----------------------------------------------------
extern "C" void kernel_launch(void* const* d_in, const int* in_sizes, int n_in,
                              void* d_out, int out_size) {
    const float* feat = (const float*)d_in[0];
    const int*   src  = (const int*)  d_in[1];
    const int*   dst  = (const int*)  d_in[2];
    const float* W1   = (const float*)d_in[3];
    const float* b1   = (const float*)d_in[4];
    const float* W2   = (const float*)d_in[5];
    const float* b2   = (const float*)d_in[6];
    const float* Wh1  = (const float*)d_in[7];
    const float* bh1  = (const float*)d_in[8];
    const float* Wh2  = (const float*)d_in[9];
    const float* bh2  = (const float*)d_in[10];
    float* out = (float*)d_out;

    int n = in_sizes[0] / DF;
    int e = in_sizes[1];

    // --- CSR build + norms (fresh every launch; no caching allowed) ---
    zero_kernel   <<<(n + 255) / 256, 256>>>(n);
    deg_kernel    <<<(e + 255) / 256, 256>>>(src, dst, e);
    norm_kernel   <<<(n + 255) / 256, 256>>>(n);
    scan_kernel   <<<1, 1024>>>(n);
    scatter_kernel<<<(e + 255) / 256, 256>>>(src, dst, e);
    initfs_kernel <<<(n * DF + 255) / 256, 256>>>(feat, n);

    // --- 20 propagation steps (2 APPNP phases of K=10) ---
    int step_blocks = (n + 7) / 8;  // 8 warps (nodes) per 256-thread block
    int ab = 0;
    for (int s = 0; s < 10; s++) {
        appnp_step<<<step_blocks, 256>>>(feat, ab, (s == 9) ? 1 : 0, n);
        ab ^= 1;
    }
    for (int s = 0; s < 10; s++) {
        appnp_step<<<step_blocks, 256>>>(nullptr, ab, (s == 9) ? 2 : 0, n);
        ab ^= 1;
    }

    // --- MLP trunk + head (fp32 SGEMMs) ---
    void *pF2, *pT1, *pT2;
    cudaGetSymbolAddress(&pF2, g_F2);
    cudaGetSymbolAddress(&pT1, g_t1);
    cudaGetSymbolAddress(&pT2, g_t2);
    float* F2 = (float*)pF2;
    float* T1 = (float*)pT1;
    float* T2 = (float*)pT2;
    float* h_last = out + (size_t)n * CCH;   // d_out = [out (N*40)] [h_last (N*128)]

    int gb = (n + 63) / 64;
    gemm_kernel<DF,  HH,  true ><<<gb, 256>>>(F2,     W1,  b1,  T1,     n);
    gemm_kernel<HH,  HH,  false><<<gb, 256>>>(T1,     W2,  b2,  h_last, n);
    gemm_kernel<HH,  HHF, true ><<<gb, 256>>>(h_last, Wh1, bh1, T2,     n);
    gemm_kernel<HHF, CCH, false><<<gb, 256>>>(T2,     Wh2, bh2, out,    n);
}

// round 3
// speedup vs baseline: 1.3043x; 1.3043x over previous
#include <cuda_runtime.h>
#include <cuda_bf16.h>
#include <math.h>

// ---------------- static problem sizes (from reference setup_inputs) -------
#define NMAX 100352      // >= N=100000
#define EMAX 1000448     // >= E=1000000
#define DF   64          // input feature dim
#define HH   128         // hidden
#define HHF  64          // H/2
#define CCH  40          // classes

// ---------------- device scratch (no allocations allowed) ------------------
__device__ float g_F1 [NMAX * DF];   // phase-1 result -> phase-2 feat_0
__device__ float g_F2 [NMAX * DF];   // phase-2 result (h) -> MLP input
__device__ float g_FSa[NMAX * DF];   // scaled feature ping
__device__ float g_FSb[NMAX * DF];   // scaled feature pong
__device__ float g_t1 [NMAX * HH];   // MLP intermediate
__device__ float g_t2 [NMAX * HHF];  // MLP intermediate
__device__ int   g_din [NMAX];
__device__ int   g_dout[NMAX];
__device__ int   g_cur [NMAX];
__device__ int   g_rowptr[NMAX];
__device__ int   g_csrc[EMAX];
__device__ float g_snorm[NMAX];
__device__ float g_dnorm[NMAX];
__device__ int   g_total;

// ---------------- preprocessing kernels ------------------------------------
__global__ void zero_kernel(int n) {
    int i = blockIdx.x * blockDim.x + threadIdx.x;
    if (i < n) { g_din[i] = 0; g_dout[i] = 0; g_cur[i] = 0; }
    if (i == 0) g_total = 0;
}

__global__ void deg_kernel(const int* __restrict__ src, const int* __restrict__ dst, int e) {
    int i = blockIdx.x * blockDim.x + threadIdx.x;
    if (i < e) {
        atomicAdd(&g_dout[src[i]], 1);
        atomicAdd(&g_din [dst[i]], 1);
    }
}

__global__ void norm_kernel(int n) {
    int i = blockIdx.x * blockDim.x + threadIdx.x;
    if (i < n) {
        int o = g_dout[i];
        int d = g_din[i];
        g_snorm[i] = (o > 0) ? rsqrtf((float)o) : 0.0f;
        g_dnorm[i] = (d > 0) ? rsqrtf((float)d) : 0.0f;
    }
}

// Assign each node a contiguous span of size din[i] via warp-aggregated atomic.
// Spans are NOT in node order — irrelevant for correctness, kills the scan.
__global__ void offset_kernel(int n) {
    int i = blockIdx.x * blockDim.x + threadIdx.x;
    int lane = threadIdx.x & 31;
    int d = (i < n) ? g_din[i] : 0;
    // warp inclusive scan
    int x = d;
#pragma unroll
    for (int off = 1; off < 32; off <<= 1) {
        int y = __shfl_up_sync(0xffffffffu, x, off);
        if (lane >= off) x += y;
    }
    int tot = __shfl_sync(0xffffffffu, x, 31);
    int base = 0;
    if (lane == 31) base = atomicAdd(&g_total, tot);
    base = __shfl_sync(0xffffffffu, base, 31);
    if (i < n) g_rowptr[i] = base + x - d;   // exclusive prefix within warp
}

__global__ void scatter_kernel(const int* __restrict__ src, const int* __restrict__ dst, int e) {
    int i = blockIdx.x * blockDim.x + threadIdx.x;
    if (i < e) {
        int d = dst[i];
        int p = g_rowptr[d] + atomicAdd(&g_cur[d], 1);
        g_csrc[p] = src[i];
    }
}

__global__ void initfs_kernel(const float* __restrict__ feat, int n) {
    int i = blockIdx.x * blockDim.x + threadIdx.x;
    if (i < n * DF) {
        int node = i >> 6;
        g_FSa[i] = feat[i] * g_snorm[node];
    }
}

// ---------------- APPNP propagation step (warp-per-node, pull/CSR) ---------
// FO: 0 none, 1 -> also write unscaled f into g_F1, 2 -> into g_F2
template<int FO>
__global__ __launch_bounds__(256) void appnp_step(const float* __restrict__ f0,
                                                  const float* __restrict__ fs_in,
                                                  float* __restrict__ fs_out,
                                                  int n) {
    int node = blockIdx.x * 8 + (threadIdx.x >> 5);
    if (node >= n) return;
    int lane = threadIdx.x & 31;

    int beg = g_rowptr[node];
    int end = beg + g_din[node];
    int off2 = 2 * lane;                   // this lane owns cols 2*lane, 2*lane+1

    float ax = 0.0f, ay = 0.0f, bx = 0.0f, by = 0.0f;
    int e = beg;
    for (; e + 4 <= end; e += 4) {         // 4 independent 256B row-reads in flight
        int s0 = __ldg(&g_csrc[e]);
        int s1 = __ldg(&g_csrc[e + 1]);
        int s2 = __ldg(&g_csrc[e + 2]);
        int s3 = __ldg(&g_csrc[e + 3]);
        float2 v0 = *(const float2*)(fs_in + (size_t)s0 * DF + off2);
        float2 v1 = *(const float2*)(fs_in + (size_t)s1 * DF + off2);
        float2 v2 = *(const float2*)(fs_in + (size_t)s2 * DF + off2);
        float2 v3 = *(const float2*)(fs_in + (size_t)s3 * DF + off2);
        ax += v0.x; ay += v0.y; bx += v1.x; by += v1.y;
        ax += v2.x; ay += v2.y; bx += v3.x; by += v3.y;
    }
    for (; e < end; e++) {
        int s = __ldg(&g_csrc[e]);
        float2 v = *(const float2*)(fs_in + (size_t)s * DF + off2);
        ax += v.x; ay += v.y;
    }
    ax += bx; ay += by;

    float dn = g_dnorm[node];
    float sn = g_snorm[node];
    size_t o = (size_t)node * DF + off2;
    float2 f0v = *(const float2*)(f0 + o);
    float fx = 0.9f * ax * dn + 0.1f * f0v.x;
    float fy = 0.9f * ay * dn + 0.1f * f0v.y;

    *(float2*)(fs_out + o) = make_float2(fx * sn, fy * sn);
    if (FO == 1) *(float2*)(g_F1 + o) = make_float2(fx, fy);
    if (FO == 2) *(float2*)(g_F2 + o) = make_float2(fx, fy);
}

// ---------------- register-tiled SGEMM: C = [relu](A[MxK] @ W[KxNC] + b) ----
// 256 threads, 64-row x NC-col block tile. Thread computes TM rows x 4 cols.
// A tile stored k-major (sAT[k][row]) so per-thread row loads are float2,
// and (warp = one ty for NC=128) uniform-broadcast -> cheap LDS.
template<int K, int NC, bool RELU>
__global__ __launch_bounds__(256) void gemm_tiled(const float* __restrict__ A,
                                                  const float* __restrict__ W,
                                                  const float* __restrict__ bias,
                                                  float* __restrict__ C, int M) {
    constexpr int TX = NC / 4;       // 32 (NC=128) or 16 (NC=64)
    constexpr int TY = 256 / TX;     // 8 or 16
    constexpr int TM = 64 / TY;      // 8 or 4
    __shared__ float sAT[32][66];    // [k][row]; stride 66: 8B-aligned, 2-way max
    __shared__ float sW[32][NC];

    int tid = threadIdx.x;
    int tx = tid % TX;
    int ty = tid / TX;
    int rowBase = blockIdx.x * 64;

    float acc[TM][4];
#pragma unroll
    for (int m = 0; m < TM; m++)
#pragma unroll
        for (int j = 0; j < 4; j++) acc[m][j] = 0.0f;

    for (int kk = 0; kk < K; kk += 32) {
        for (int i = tid; i < 64 * 32; i += 256) {
            int r = i >> 5, k = i & 31;
            int gr = rowBase + r;
            sAT[k][r] = (gr < M) ? A[(size_t)gr * K + kk + k] : 0.0f;
        }
        for (int i = tid; i < 32 * NC; i += 256) {
            int k = i / NC, c = i % NC;
            sW[k][c] = W[(size_t)(kk + k) * NC + c];
        }
        __syncthreads();
#pragma unroll
        for (int k = 0; k < 32; k++) {
            float4 w = *(const float4*)&sW[k][tx * 4];
            float a[TM];
#pragma unroll
            for (int m2 = 0; m2 < TM / 2; m2++) {
                float2 t = *(const float2*)&sAT[k][ty * TM + 2 * m2];
                a[2 * m2] = t.x; a[2 * m2 + 1] = t.y;
            }
#pragma unroll
            for (int m = 0; m < TM; m++) {
                acc[m][0] += a[m] * w.x;
                acc[m][1] += a[m] * w.y;
                acc[m][2] += a[m] * w.z;
                acc[m][3] += a[m] * w.w;
            }
        }
        __syncthreads();
    }

    float4 bv = *(const float4*)&bias[tx * 4];
#pragma unroll
    for (int m = 0; m < TM; m++) {
        int gr = rowBase + ty * TM + m;
        if (gr < M) {
            float4 v;
            v.x = acc[m][0] + bv.x;
            v.y = acc[m][1] + bv.y;
            v.z = acc[m][2] + bv.z;
            v.w = acc[m][3] + bv.w;
            if (RELU) {
                v.x = fmaxf(v.x, 0.0f); v.y = fmaxf(v.y, 0.0f);
                v.z = fmaxf(v.z, 0.0f); v.w = fmaxf(v.w, 0.0f);
            }
            *(float4*)&C[(size_t)gr * NC + tx * 4] = v;
        }
    }
}

// naive GEMM kept for the small head layer (K=64, NC=40)
template<int K, int NC, bool RELU>
__global__ __launch_bounds__(256) void gemm_small(const float* __restrict__ A,
                                                  const float* __restrict__ W,
                                                  const float* __restrict__ bias,
                                                  float* __restrict__ C, int M) {
    __shared__ float sA[64][33];
    __shared__ float sW[32][NC];
    const int CPT = NC / 4;
    float acc[CPT];
    int tid = threadIdx.x;
    int r  = tid >> 2;
    int cg = tid & 3;
    int row = blockIdx.x * 64 + r;
#pragma unroll
    for (int c = 0; c < CPT; c++) acc[c] = 0.0f;

    for (int kk = 0; kk < K; kk += 32) {
        for (int i = tid; i < 64 * 32; i += 256) {
            int rr = i >> 5, kx = i & 31;
            int grow = blockIdx.x * 64 + rr;
            sA[rr][kx] = (grow < M) ? A[(size_t)grow * K + kk + kx] : 0.0f;
        }
        for (int i = tid; i < 32 * NC; i += 256) {
            int kx = i / NC, cx = i % NC;
            sW[kx][cx] = W[(size_t)(kk + kx) * NC + cx];
        }
        __syncthreads();
#pragma unroll
        for (int k = 0; k < 32; k++) {
            float a = sA[r][k];
#pragma unroll
            for (int c = 0; c < CPT; c++) acc[c] += a * sW[k][c * 4 + cg];
        }
        __syncthreads();
    }

    if (row < M) {
#pragma unroll
        for (int c = 0; c < CPT; c++) {
            float v = acc[c] + bias[c * 4 + cg];
            if (RELU) v = fmaxf(v, 0.0f);
            C[(size_t)row * NC + c * 4 + cg] = v;
        }
    }
}

// ---------------- launch ----------------------------------------------------
extern "C" void kernel_launch(void* const* d_in, const int* in_sizes, int n_in,
                              void* d_out, int out_size) {
    const float* feat = (const float*)d_in[0];
    const int*   src  = (const int*)  d_in[1];
    const int*   dst  = (const int*)  d_in[2];
    const float* W1   = (const float*)d_in[3];
    const float* b1   = (const float*)d_in[4];
    const float* W2   = (const float*)d_in[5];
    const float* b2   = (const float*)d_in[6];
    const float* Wh1  = (const float*)d_in[7];
    const float* bh1  = (const float*)d_in[8];
    const float* Wh2  = (const float*)d_in[9];
    const float* bh2  = (const float*)d_in[10];
    float* out = (float*)d_out;

    int n = in_sizes[0] / DF;
    int e = in_sizes[1];

    void *pF1, *pF2, *pFa, *pFb, *pT1, *pT2;
    cudaGetSymbolAddress(&pF1, g_F1);
    cudaGetSymbolAddress(&pF2, g_F2);
    cudaGetSymbolAddress(&pFa, g_FSa);
    cudaGetSymbolAddress(&pFb, g_FSb);
    cudaGetSymbolAddress(&pT1, g_t1);
    cudaGetSymbolAddress(&pT2, g_t2);
    float* F1 = (float*)pF1;
    float* F2 = (float*)pF2;
    float* FSa = (float*)pFa;
    float* FSb = (float*)pFb;
    float* T1 = (float*)pT1;
    float* T2 = (float*)pT2;

    // --- CSR build + norms (fresh every launch; no caching allowed) ---
    zero_kernel   <<<(n + 255) / 256, 256>>>(n);
    deg_kernel    <<<(e + 255) / 256, 256>>>(src, dst, e);
    norm_kernel   <<<(n + 255) / 256, 256>>>(n);
    offset_kernel <<<(n + 255) / 256, 256>>>(n);
    scatter_kernel<<<(e + 255) / 256, 256>>>(src, dst, e);
    initfs_kernel <<<(n * DF + 255) / 256, 256>>>(feat, n);

    // --- 20 propagation steps (2 APPNP phases of K=10) ---
    int step_blocks = (n + 7) / 8;  // 8 warps (nodes) per 256-thread block
    float* fin = FSa; float* fout = FSb;
    for (int s = 0; s < 10; s++) {
        if (s == 9) appnp_step<1><<<step_blocks, 256>>>(feat, fin, fout, n);
        else        appnp_step<0><<<step_blocks, 256>>>(feat, fin, fout, n);
        float* t = fin; fin = fout; fout = t;
    }
    for (int s = 0; s < 10; s++) {
        if (s == 9) appnp_step<2><<<step_blocks, 256>>>(F1, fin, fout, n);
        else        appnp_step<0><<<step_blocks, 256>>>(F1, fin, fout, n);
        float* t = fin; fin = fout; fout = t;
    }

    // --- MLP trunk + head (fp32 SGEMMs) ---
    float* h_last = out + (size_t)n * CCH;   // d_out = [out (N*40)] [h_last (N*128)]
    int gb = (n + 63) / 64;
    gemm_tiled<DF,  HH,  true ><<<gb, 256>>>(F2,     W1,  b1,  T1,     n);
    gemm_tiled<HH,  HH,  false><<<gb, 256>>>(T1,     W2,  b2,  h_last, n);
    gemm_tiled<HH,  HHF, true ><<<gb, 256>>>(h_last, Wh1, bh1, T2,     n);
    gemm_small<HHF, CCH, false><<<gb, 256>>>(T2,     Wh2, bh2, out,    n);
}

// round 4
// speedup vs baseline: 1.4356x; 1.1006x over previous
#include <cuda_runtime.h>
#include <cuda_fp16.h>
#include <math.h>

// ---------------- static problem sizes (from reference setup_inputs) -------
#define NMAX 100352      // >= N=100000
#define EMAX 1000448     // >= E=1000000
#define DF   64          // input feature dim
#define DF2  32          // half2 elements per row
#define HH   128         // hidden
#define HHF  64          // H/2
#define CCH  40          // classes

// ---------------- device scratch (no allocations allowed) ------------------
__device__ float   g_F1 [NMAX * DF];    // phase-1 result -> phase-2 feat_0 (fp32)
__device__ float   g_F2 [NMAX * DF];    // phase-2 result (h) -> MLP input (fp32)
__device__ __half2 g_FSa[NMAX * DF2];   // scaled feature ping (fp16)
__device__ __half2 g_FSb[NMAX * DF2];   // scaled feature pong (fp16)
__device__ float   g_t1 [NMAX * HH];    // MLP intermediate
__device__ float   g_t2 [NMAX * HHF];   // MLP intermediate
__device__ int     g_din [NMAX];
__device__ int     g_dout[NMAX];
__device__ int     g_cur [NMAX];
__device__ int     g_rowptr[NMAX];
__device__ int     g_csrc[EMAX];
__device__ float   g_snorm[NMAX];
__device__ float   g_dnorm[NMAX];
__device__ int     g_total;

// ---------------- preprocessing kernels ------------------------------------
__global__ void zero_kernel(int n) {
    int i = blockIdx.x * blockDim.x + threadIdx.x;
    if (i < n) { g_din[i] = 0; g_dout[i] = 0; g_cur[i] = 0; }
    if (i == 0) g_total = 0;
}

__global__ void deg_kernel(const int* __restrict__ src, const int* __restrict__ dst, int e) {
    int i = blockIdx.x * blockDim.x + threadIdx.x;
    if (i < e) {
        atomicAdd(&g_dout[src[i]], 1);
        atomicAdd(&g_din [dst[i]], 1);
    }
}

__global__ void norm_kernel(int n) {
    int i = blockIdx.x * blockDim.x + threadIdx.x;
    if (i < n) {
        int o = g_dout[i];
        int d = g_din[i];
        g_snorm[i] = (o > 0) ? rsqrtf((float)o) : 0.0f;
        g_dnorm[i] = (d > 0) ? rsqrtf((float)d) : 0.0f;
    }
}

// Assign each node a contiguous span of size din[i] via warp-aggregated atomic.
// Spans are NOT in node order — irrelevant for correctness, kills the scan.
__global__ void offset_kernel(int n) {
    int i = blockIdx.x * blockDim.x + threadIdx.x;
    int lane = threadIdx.x & 31;
    int d = (i < n) ? g_din[i] : 0;
    int x = d;
#pragma unroll
    for (int off = 1; off < 32; off <<= 1) {
        int y = __shfl_up_sync(0xffffffffu, x, off);
        if (lane >= off) x += y;
    }
    int tot = __shfl_sync(0xffffffffu, x, 31);
    int base = 0;
    if (lane == 31) base = atomicAdd(&g_total, tot);
    base = __shfl_sync(0xffffffffu, base, 31);
    if (i < n) g_rowptr[i] = base + x - d;   // exclusive prefix within warp
}

__global__ void scatter_kernel(const int* __restrict__ src, const int* __restrict__ dst, int e) {
    int i = blockIdx.x * blockDim.x + threadIdx.x;
    if (i < e) {
        int d = dst[i];
        int p = g_rowptr[d] + atomicAdd(&g_cur[d], 1);
        g_csrc[p] = src[i];
    }
}

__global__ void initfs_kernel(const float* __restrict__ feat, int n) {
    int i = blockIdx.x * blockDim.x + threadIdx.x;   // one half2 per thread
    if (i < n * DF2) {
        int node = i >> 5;
        float sn = g_snorm[node];
        float2 v = *(const float2*)(feat + 2 * (size_t)i);
        g_FSa[i] = __float22half2_rn(make_float2(v.x * sn, v.y * sn));
    }
}

// ---------------- APPNP propagation step (warp-per-node, pull/CSR) ---------
// Gathers fp16-scaled rows, accumulates fp32.
// FO: 0 none, 1 -> also write unscaled fp32 f into g_F1, 2 -> into g_F2
template<int FO>
__global__ __launch_bounds__(256) void appnp_step(const float* __restrict__ f0,
                                                  const __half2* __restrict__ fs_in,
                                                  __half2* __restrict__ fs_out,
                                                  int n) {
    int node = blockIdx.x * 8 + (threadIdx.x >> 5);
    if (node >= n) return;
    int lane = threadIdx.x & 31;          // lane owns half2 column `lane` (cols 2l, 2l+1)

    int beg = g_rowptr[node];
    int end = beg + g_din[node];

    float a0x = 0.f, a0y = 0.f, a1x = 0.f, a1y = 0.f;
    float a2x = 0.f, a2y = 0.f, a3x = 0.f, a3y = 0.f;
    int e = beg;
    for (; e + 8 <= end; e += 8) {        // 8 independent 128B row-reads in flight
        int s0 = __ldg(&g_csrc[e]);
        int s1 = __ldg(&g_csrc[e + 1]);
        int s2 = __ldg(&g_csrc[e + 2]);
        int s3 = __ldg(&g_csrc[e + 3]);
        int s4 = __ldg(&g_csrc[e + 4]);
        int s5 = __ldg(&g_csrc[e + 5]);
        int s6 = __ldg(&g_csrc[e + 6]);
        int s7 = __ldg(&g_csrc[e + 7]);
        float2 v0 = __half22float2(__ldg(&fs_in[(size_t)s0 * DF2 + lane]));
        float2 v1 = __half22float2(__ldg(&fs_in[(size_t)s1 * DF2 + lane]));
        float2 v2 = __half22float2(__ldg(&fs_in[(size_t)s2 * DF2 + lane]));
        float2 v3 = __half22float2(__ldg(&fs_in[(size_t)s3 * DF2 + lane]));
        float2 v4 = __half22float2(__ldg(&fs_in[(size_t)s4 * DF2 + lane]));
        float2 v5 = __half22float2(__ldg(&fs_in[(size_t)s5 * DF2 + lane]));
        float2 v6 = __half22float2(__ldg(&fs_in[(size_t)s6 * DF2 + lane]));
        float2 v7 = __half22float2(__ldg(&fs_in[(size_t)s7 * DF2 + lane]));
        a0x += v0.x; a0y += v0.y; a1x += v1.x; a1y += v1.y;
        a2x += v2.x; a2y += v2.y; a3x += v3.x; a3y += v3.y;
        a0x += v4.x; a0y += v4.y; a1x += v5.x; a1y += v5.y;
        a2x += v6.x; a2y += v6.y; a3x += v7.x; a3y += v7.y;
    }
    for (; e < end; e++) {
        int s = __ldg(&g_csrc[e]);
        float2 v = __half22float2(__ldg(&fs_in[(size_t)s * DF2 + lane]));
        a0x += v.x; a0y += v.y;
    }
    float ax = (a0x + a1x) + (a2x + a3x);
    float ay = (a0y + a1y) + (a2y + a3y);

    float dn = g_dnorm[node];
    float sn = g_snorm[node];
    size_t o = (size_t)node * DF + 2 * lane;
    float2 f0v = *(const float2*)(f0 + o);
    float fx = 0.9f * ax * dn + 0.1f * f0v.x;
    float fy = 0.9f * ay * dn + 0.1f * f0v.y;

    fs_out[(size_t)node * DF2 + lane] = __float22half2_rn(make_float2(fx * sn, fy * sn));
    if (FO == 1) *(float2*)(g_F1 + o) = make_float2(fx, fy);
    if (FO == 2) *(float2*)(g_F2 + o) = make_float2(fx, fy);
}

// ---------------- register-tiled SGEMM: C = [relu](A[MxK] @ W[KxNC] + b) ----
template<int K, int NC, bool RELU>
__global__ __launch_bounds__(256) void gemm_tiled(const float* __restrict__ A,
                                                  const float* __restrict__ W,
                                                  const float* __restrict__ bias,
                                                  float* __restrict__ C, int M) {
    constexpr int TX = NC / 4;       // 32 (NC=128) or 16 (NC=64)
    constexpr int TY = 256 / TX;     // 8 or 16
    constexpr int TM = 64 / TY;      // 8 or 4
    __shared__ float sAT[32][66];    // [k][row]
    __shared__ float sW[32][NC];

    int tid = threadIdx.x;
    int tx = tid % TX;
    int ty = tid / TX;
    int rowBase = blockIdx.x * 64;

    float acc[TM][4];
#pragma unroll
    for (int m = 0; m < TM; m++)
#pragma unroll
        for (int j = 0; j < 4; j++) acc[m][j] = 0.0f;

    for (int kk = 0; kk < K; kk += 32) {
        for (int i = tid; i < 64 * 32; i += 256) {
            int r = i >> 5, k = i & 31;
            int gr = rowBase + r;
            sAT[k][r] = (gr < M) ? A[(size_t)gr * K + kk + k] : 0.0f;
        }
        for (int i = tid; i < 32 * NC; i += 256) {
            int k = i / NC, c = i % NC;
            sW[k][c] = W[(size_t)(kk + k) * NC + c];
        }
        __syncthreads();
#pragma unroll
        for (int k = 0; k < 32; k++) {
            float4 w = *(const float4*)&sW[k][tx * 4];
            float a[TM];
#pragma unroll
            for (int m2 = 0; m2 < TM / 2; m2++) {
                float2 t = *(const float2*)&sAT[k][ty * TM + 2 * m2];
                a[2 * m2] = t.x; a[2 * m2 + 1] = t.y;
            }
#pragma unroll
            for (int m = 0; m < TM; m++) {
                acc[m][0] += a[m] * w.x;
                acc[m][1] += a[m] * w.y;
                acc[m][2] += a[m] * w.z;
                acc[m][3] += a[m] * w.w;
            }
        }
        __syncthreads();
    }

    float4 bv = *(const float4*)&bias[tx * 4];
#pragma unroll
    for (int m = 0; m < TM; m++) {
        int gr = rowBase + ty * TM + m;
        if (gr < M) {
            float4 v;
            v.x = acc[m][0] + bv.x;
            v.y = acc[m][1] + bv.y;
            v.z = acc[m][2] + bv.z;
            v.w = acc[m][3] + bv.w;
            if (RELU) {
                v.x = fmaxf(v.x, 0.0f); v.y = fmaxf(v.y, 0.0f);
                v.z = fmaxf(v.z, 0.0f); v.w = fmaxf(v.w, 0.0f);
            }
            *(float4*)&C[(size_t)gr * NC + tx * 4] = v;
        }
    }
}

// naive GEMM kept for the small head layer (K=64, NC=40)
template<int K, int NC, bool RELU>
__global__ __launch_bounds__(256) void gemm_small(const float* __restrict__ A,
                                                  const float* __restrict__ W,
                                                  const float* __restrict__ bias,
                                                  float* __restrict__ C, int M) {
    __shared__ float sA[64][33];
    __shared__ float sW[32][NC];
    const int CPT = NC / 4;
    float acc[CPT];
    int tid = threadIdx.x;
    int r  = tid >> 2;
    int cg = tid & 3;
    int row = blockIdx.x * 64 + r;
#pragma unroll
    for (int c = 0; c < CPT; c++) acc[c] = 0.0f;

    for (int kk = 0; kk < K; kk += 32) {
        for (int i = tid; i < 64 * 32; i += 256) {
            int rr = i >> 5, kx = i & 31;
            int grow = blockIdx.x * 64 + rr;
            sA[rr][kx] = (grow < M) ? A[(size_t)grow * K + kk + kx] : 0.0f;
        }
        for (int i = tid; i < 32 * NC; i += 256) {
            int kx = i / NC, cx = i % NC;
            sW[kx][cx] = W[(size_t)(kk + kx) * NC + cx];
        }
        __syncthreads();
#pragma unroll
        for (int k = 0; k < 32; k++) {
            float a = sA[r][k];
#pragma unroll
            for (int c = 0; c < CPT; c++) acc[c] += a * sW[k][c * 4 + cg];
        }
        __syncthreads();
    }

    if (row < M) {
#pragma unroll
        for (int c = 0; c < CPT; c++) {
            float v = acc[c] + bias[c * 4 + cg];
            if (RELU) v = fmaxf(v, 0.0f);
            C[(size_t)row * NC + c * 4 + cg] = v;
        }
    }
}

// ---------------- launch ----------------------------------------------------
extern "C" void kernel_launch(void* const* d_in, const int* in_sizes, int n_in,
                              void* d_out, int out_size) {
    const float* feat = (const float*)d_in[0];
    const int*   src  = (const int*)  d_in[1];
    const int*   dst  = (const int*)  d_in[2];
    const float* W1   = (const float*)d_in[3];
    const float* b1   = (const float*)d_in[4];
    const float* W2   = (const float*)d_in[5];
    const float* b2   = (const float*)d_in[6];
    const float* Wh1  = (const float*)d_in[7];
    const float* bh1  = (const float*)d_in[8];
    const float* Wh2  = (const float*)d_in[9];
    const float* bh2  = (const float*)d_in[10];
    float* out = (float*)d_out;

    int n = in_sizes[0] / DF;
    int e = in_sizes[1];

    void *pF1, *pF2, *pFa, *pFb, *pT1, *pT2;
    cudaGetSymbolAddress(&pF1, g_F1);
    cudaGetSymbolAddress(&pF2, g_F2);
    cudaGetSymbolAddress(&pFa, g_FSa);
    cudaGetSymbolAddress(&pFb, g_FSb);
    cudaGetSymbolAddress(&pT1, g_t1);
    cudaGetSymbolAddress(&pT2, g_t2);
    float*   F1  = (float*)pF1;
    float*   F2  = (float*)pF2;
    __half2* FSa = (__half2*)pFa;
    __half2* FSb = (__half2*)pFb;
    float*   T1  = (float*)pT1;
    float*   T2  = (float*)pT2;

    // --- CSR build + norms (fresh every launch; no caching allowed) ---
    zero_kernel   <<<(n + 255) / 256, 256>>>(n);
    deg_kernel    <<<(e + 255) / 256, 256>>>(src, dst, e);
    norm_kernel   <<<(n + 255) / 256, 256>>>(n);
    offset_kernel <<<(n + 255) / 256, 256>>>(n);
    scatter_kernel<<<(e + 255) / 256, 256>>>(src, dst, e);
    initfs_kernel <<<(n * DF2 + 255) / 256, 256>>>(feat, n);

    // --- 20 propagation steps (2 APPNP phases of K=10) ---
    int step_blocks = (n + 7) / 8;  // 8 warps (nodes) per 256-thread block
    __half2* fin = FSa; __half2* fout = FSb;
    for (int s = 0; s < 10; s++) {
        if (s == 9) appnp_step<1><<<step_blocks, 256>>>(feat, fin, fout, n);
        else        appnp_step<0><<<step_blocks, 256>>>(feat, fin, fout, n);
        __half2* t = fin; fin = fout; fout = t;
    }
    for (int s = 0; s < 10; s++) {
        if (s == 9) appnp_step<2><<<step_blocks, 256>>>(F1, fin, fout, n);
        else        appnp_step<0><<<step_blocks, 256>>>(F1, fin, fout, n);
        __half2* t = fin; fin = fout; fout = t;
    }

    // --- MLP trunk + head (fp32 SGEMMs) ---
    float* h_last = out + (size_t)n * CCH;   // d_out = [out (N*40)] [h_last (N*128)]
    int gb = (n + 63) / 64;
    gemm_tiled<DF,  HH,  true ><<<gb, 256>>>(F2,     W1,  b1,  T1,     n);
    gemm_tiled<HH,  HH,  false><<<gb, 256>>>(T1,     W2,  b2,  h_last, n);
    gemm_tiled<HH,  HHF, true ><<<gb, 256>>>(h_last, Wh1, bh1, T2,     n);
    gemm_small<HHF, CCH, false><<<gb, 256>>>(T2,     Wh2, bh2, out,    n);
}